// round 6
// baseline (speedup 1.0000x reference)
#include <cuda_runtime.h>
#include <cuda_bf16.h>

// Problem constants
#define BATCH 8
#define SQ 2048
#define SK 2048
#define DIM 1024
#define H 8
#define ROWS (BATCH * SQ)   // 16384
#define KSPLIT 8
#define KS_LEN (SK / KSPLIT)  // 256

// Scratch (allocation-free: __device__ globals)
__device__ float g_q[ROWS * H];
__device__ float g_k[ROWS * H];
__device__ float g_v[ROWS * H];
__device__ float g_pn[KSPLIT * ROWS * H];  // partial numerators
__device__ float g_pd[KSPLIT * ROWS];      // partial denominators

typedef unsigned long long ull;

__device__ __forceinline__ ull ffma2(ull a, ull b, ull c) {
    ull d;
    asm("fma.rn.f32x2 %0, %1, %2, %3;" : "=l"(d) : "l"(a), "l"(b), "l"(c));
    return d;
}
__device__ __forceinline__ ull fmul2(ull a, ull b) {
    ull d;
    asm("mul.rn.f32x2 %0, %1, %2;" : "=l"(d) : "l"(a), "l"(b));
    return d;
}
__device__ __forceinline__ float f2_lo(ull a) { return __uint_as_float((unsigned)(a & 0xffffffffull)); }
__device__ __forceinline__ float f2_hi(ull a) { return __uint_as_float((unsigned)(a >> 32)); }
__device__ __forceinline__ ull f2_pack(float lo, float hi) {
    ull p;
    asm("mov.b64 %0, {%1, %2};" : "=l"(p) : "r"(__float_as_uint(lo)), "r"(__float_as_uint(hi)));
    return p;
}

// ---------------------------------------------------------------------------
// Kernel 1: fused q/k/v projection. grid = 3 * 256 blocks x 256 threads.
//   path = blockIdx.x >> 8 selects (X, W, bias, Y). 64 rows/block,
//   8 rows/warp as four batches of two. Per batch, BOTH full rows of x are
//   front-loaded into registers (16 back-to-back LDG.128 -> MLP=16) before
//   any FMA, removing the per-u DRAM round-trip stall seen in R5.
//   W transposed in smem (+8 pad), staged with float4 loads.
// ---------------------------------------------------------------------------
#define PROJ_WPITCH 1032   // 1024 + 8 pad floats
__global__ void __launch_bounds__(256, 2) proj_fused_kernel(
    const float* __restrict__ x, const float* __restrict__ ctx,
    const float* __restrict__ Wq, const float* __restrict__ bq,
    const float* __restrict__ Wk, const float* __restrict__ bk,
    const float* __restrict__ Wv, const float* __restrict__ bv,
    float* __restrict__ q, float* __restrict__ k, float* __restrict__ v)
{
    __shared__ float sw[H * PROJ_WPITCH];   // 33 KB

    const int tid = threadIdx.x;
    const int warp = tid >> 5;
    const int lane = tid & 31;

    const int path = blockIdx.x >> 8;       // 0 = q, 1 = k, 2 = v
    const int blk  = blockIdx.x & 255;

    const float* X    = (path == 0) ? x  : ctx;
    const float* W    = (path == 0) ? Wq : (path == 1) ? Wk : Wv;
    const float* bias = (path == 0) ? bq : (path == 1) ? bk : bv;
    float*       Y    = (path == 0) ? q  : (path == 1) ? k  : v;

    // Stage W transposed via float4 global loads:
    //   i in [0, 2048): d = i>>1, hg = (i&1)*4 -> W[d*8 + hg .. +4]
    for (int i = tid; i < DIM * 2; i += 256) {
        int d = i >> 1, hg = (i & 1) * 4;
        float4 w4 = *reinterpret_cast<const float4*>(W + d * H + hg);
        sw[(hg + 0) * PROJ_WPITCH + d] = w4.x;
        sw[(hg + 1) * PROJ_WPITCH + d] = w4.y;
        sw[(hg + 2) * PROJ_WPITCH + d] = w4.z;
        sw[(hg + 3) * PROJ_WPITCH + d] = w4.w;
    }
    float bias_lane = (lane < H) ? bias[lane] : 0.0f;
    __syncthreads();

    const int block_row0 = blk * 64;

#pragma unroll 1
    for (int b2 = 0; b2 < 4; ++b2) {
        const int row0 = block_row0 + warp * 8 + b2 * 2;
        const float* xr0 = X + (size_t)row0 * DIM + lane * 4;

        // Front-batched loads: both rows, all 8 chunks (16 LDG.128 in flight)
        ulonglong2 xv0[8], xv1[8];
#pragma unroll
        for (int u = 0; u < 8; ++u)
            xv0[u] = *reinterpret_cast<const ulonglong2*>(xr0 + u * 128);
#pragma unroll
        for (int u = 0; u < 8; ++u)
            xv1[u] = *reinterpret_cast<const ulonglong2*>(xr0 + DIM + u * 128);

        ull acc0[H], acc1[H];
#pragma unroll
        for (int h = 0; h < H; ++h) { acc0[h] = 0ull; acc1[h] = 0ull; }

#pragma unroll
        for (int u = 0; u < 8; ++u) {
            const int d = lane * 4 + u * 128;
#pragma unroll
            for (int h = 0; h < H; ++h) {
                ulonglong2 wv = *reinterpret_cast<const ulonglong2*>(&sw[h * PROJ_WPITCH + d]);
                acc0[h] = ffma2(xv0[u].x, wv.x, acc0[h]);
                acc0[h] = ffma2(xv0[u].y, wv.y, acc0[h]);
                acc1[h] = ffma2(xv1[u].x, wv.x, acc1[h]);
                acc1[h] = ffma2(xv1[u].y, wv.y, acc1[h]);
            }
        }

        // Reduce across lanes; lane h keeps head h's sum
#pragma unroll
        for (int r = 0; r < 2; ++r) {
            float keep = 0.0f;
#pragma unroll
            for (int h = 0; h < H; ++h) {
                ull a = r ? acc1[h] : acc0[h];
                float s = f2_lo(a) + f2_hi(a);
                s += __shfl_xor_sync(0xffffffffu, s, 16);
                s += __shfl_xor_sync(0xffffffffu, s, 8);
                s += __shfl_xor_sync(0xffffffffu, s, 4);
                s += __shfl_xor_sync(0xffffffffu, s, 2);
                s += __shfl_xor_sync(0xffffffffu, s, 1);
                if (lane == h) keep = s;
            }
            if (lane < H) Y[(size_t)(row0 + r) * H + lane] = keep + bias_lane;
        }
    }
}

// ---------------------------------------------------------------------------
// Kernel 2: attention partials with key-split.
//   grid = 8 batches x 16 qchunks x 8 ksplits = 1024 blocks x 128 threads.
//   One thread per query; each block covers 256 keys (tile in smem, 16 KB).
//   Softmax without max-subtraction -> split partials add exactly.
// ---------------------------------------------------------------------------
__global__ void __launch_bounds__(128) attn_part_kernel(
    const float* __restrict__ q, const float* __restrict__ k,
    const float* __restrict__ v, float* __restrict__ pn,
    float* __restrict__ pd)
{
    __shared__ float ks[KS_LEN * H];   // 8 KB
    __shared__ float vs[KS_LEN * H];   // 8 KB

    const int tid = threadIdx.x;
    const int bb = blockIdx.x >> 7;            // batch
    const int qc = (blockIdx.x >> 3) & 15;     // query chunk
    const int sp = blockIdx.x & 7;             // key split
    const int row = bb * SQ + qc * 128 + tid;
    const int kbase = bb * SK + sp * KS_LEN;

    // Cooperative tile load: 256 keys x 8 floats for k and v
    {
        const float4* kg = reinterpret_cast<const float4*>(k + (size_t)kbase * H);
        const float4* vg = reinterpret_cast<const float4*>(v + (size_t)kbase * H);
        float4* ks4 = reinterpret_cast<float4*>(ks);
        float4* vs4 = reinterpret_cast<float4*>(vs);
#pragma unroll
        for (int i = 0; i < (KS_LEN * H / 4) / 128; ++i) {
            ks4[tid + i * 128] = kg[tid + i * 128];
            vs4[tid + i * 128] = vg[tid + i * 128];
        }
    }

    // Query in registers as four f32x2 packs
    ulonglong2 qa = *reinterpret_cast<const ulonglong2*>(q + (size_t)row * H);
    ulonglong2 qb = *reinterpret_cast<const ulonglong2*>(q + (size_t)row * H + 4);
    const ull q01 = qa.x, q23 = qa.y, q45 = qb.x, q67 = qb.y;

    __syncthreads();

    ull acc0 = 0ull, acc1 = 0ull, acc2 = 0ull, acc3 = 0ull;
    float denom = 0.0f;

#pragma unroll 8
    for (int t = 0; t < KS_LEN; ++t) {
        ulonglong2 k0 = *reinterpret_cast<const ulonglong2*>(&ks[t * H]);
        ulonglong2 k1 = *reinterpret_cast<const ulonglong2*>(&ks[t * H + 4]);
        ull s2 = fmul2(q67, k1.y);
        s2 = ffma2(q45, k1.x, s2);
        s2 = ffma2(q23, k0.y, s2);
        s2 = ffma2(q01, k0.x, s2);
        float s = f2_lo(s2) + f2_hi(s2);
        float e = __expf(s);
        denom += e;
        ull e2 = f2_pack(e, e);
        ulonglong2 v0 = *reinterpret_cast<const ulonglong2*>(&vs[t * H]);
        ulonglong2 v1 = *reinterpret_cast<const ulonglong2*>(&vs[t * H + 4]);
        acc0 = ffma2(e2, v0.x, acc0);
        acc1 = ffma2(e2, v0.y, acc1);
        acc2 = ffma2(e2, v1.x, acc2);
        acc3 = ffma2(e2, v1.y, acc3);
    }

    float4 o0, o1;
    o0.x = f2_lo(acc0); o0.y = f2_hi(acc0);
    o0.z = f2_lo(acc1); o0.w = f2_hi(acc1);
    o1.x = f2_lo(acc2); o1.y = f2_hi(acc2);
    o1.z = f2_lo(acc3); o1.w = f2_hi(acc3);
    float* pnr = pn + ((size_t)sp * ROWS + row) * H;
    *reinterpret_cast<float4*>(pnr)     = o0;
    *reinterpret_cast<float4*>(pnr + 4) = o1;
    pd[(size_t)sp * ROWS + row] = denom;
}

// ---------------------------------------------------------------------------
// Kernel 3: combine split-K partials + output projection.
//   grid = 1024 blocks x 256 threads, 16 rows/block.
//   Fold parallelized: threads 0..127 each fetch one (row, split) partial
//   into smem; threads 0..15 then fold 8 splits from smem (LDS, not LDG).
//   All threads project with Wo slice in registers (8 x float4 per thread).
// ---------------------------------------------------------------------------
#define OUT_RPB 16
__global__ void __launch_bounds__(256) outproj_kernel(
    const float* __restrict__ pn, const float* __restrict__ pd,
    const float* __restrict__ Wo, const float* __restrict__ bo,
    float* __restrict__ out)
{
    __shared__ float ps[OUT_RPB][KSPLIT][12];  // 9 used, pad to 12
    __shared__ float a_sm[OUT_RPB][H];

    const int t = threadIdx.x;
    const int j = t * 4;
    const int row0 = blockIdx.x * OUT_RPB;

    if (t < OUT_RPB * KSPLIT) {
        const int r = t >> 3;
        const int s = t & 7;
        const int row = row0 + r;
        const float* p = pn + ((size_t)s * ROWS + row) * H;
        float4 a = *reinterpret_cast<const float4*>(p);
        float4 b = *reinterpret_cast<const float4*>(p + 4);
        ps[r][s][0] = a.x; ps[r][s][1] = a.y; ps[r][s][2] = a.z; ps[r][s][3] = a.w;
        ps[r][s][4] = b.x; ps[r][s][5] = b.y; ps[r][s][6] = b.z; ps[r][s][7] = b.w;
        ps[r][s][8] = pd[(size_t)s * ROWS + row];
    }

    float4 w[H];
#pragma unroll
    for (int h = 0; h < H; ++h)
        w[h] = *reinterpret_cast<const float4*>(Wo + h * DIM + j);
    const float4 b4 = *reinterpret_cast<const float4*>(bo + j);

    __syncthreads();

    if (t < OUT_RPB) {
        float n[H] = {0.f, 0.f, 0.f, 0.f, 0.f, 0.f, 0.f, 0.f};
        float den = 0.0f;
#pragma unroll
        for (int s = 0; s < KSPLIT; ++s) {
#pragma unroll
            for (int h = 0; h < H; ++h) n[h] += ps[t][s][h];
            den += ps[t][s][8];
        }
        const float inv = 1.0f / den;
#pragma unroll
        for (int h = 0; h < H; ++h) a_sm[t][h] = n[h] * inv;
    }
    __syncthreads();

#pragma unroll
    for (int r = 0; r < OUT_RPB; ++r) {
        const int row = row0 + r;
        float4 o = b4;
#pragma unroll
        for (int h = 0; h < H; ++h) {
            float ah = a_sm[r][h];
            o.x = fmaf(ah, w[h].x, o.x);
            o.y = fmaf(ah, w[h].y, o.y);
            o.z = fmaf(ah, w[h].z, o.z);
            o.w = fmaf(ah, w[h].w, o.w);
        }
        *reinterpret_cast<float4*>(out + (size_t)row * DIM + j) = o;
    }
}

// ---------------------------------------------------------------------------
extern "C" void kernel_launch(void* const* d_in, const int* in_sizes, int n_in,
                              void* d_out, int out_size)
{
    const float* x       = (const float*)d_in[0];
    const float* context = (const float*)d_in[1];
    const float* Wq      = (const float*)d_in[2];
    const float* bq      = (const float*)d_in[3];
    const float* Wk      = (const float*)d_in[4];
    const float* bk      = (const float*)d_in[5];
    const float* Wv      = (const float*)d_in[6];
    const float* bv      = (const float*)d_in[7];
    const float* Wo      = (const float*)d_in[8];
    const float* bo      = (const float*)d_in[9];
    float* out = (float*)d_out;

    float* q_p;  cudaGetSymbolAddress((void**)&q_p,  g_q);
    float* k_p;  cudaGetSymbolAddress((void**)&k_p,  g_k);
    float* v_p;  cudaGetSymbolAddress((void**)&v_p,  g_v);
    float* pn_p; cudaGetSymbolAddress((void**)&pn_p, g_pn);
    float* pd_p; cudaGetSymbolAddress((void**)&pd_p, g_pd);

    proj_fused_kernel<<<3 * 256, 256>>>(x, context, Wq, bq, Wk, bk, Wv, bv,
                                        q_p, k_p, v_p);
    attn_part_kernel<<<BATCH * 16 * KSPLIT, 128>>>(q_p, k_p, v_p, pn_p, pd_p);
    outproj_kernel<<<ROWS / OUT_RPB, 256>>>(pn_p, pd_p, Wo, bo, out);
}

// round 10
// speedup vs baseline: 2.1558x; 2.1558x over previous
#include <cuda_runtime.h>
#include <cuda_bf16.h>

// Problem constants
#define BATCH 8
#define SQ 2048
#define SK 2048
#define DIM 1024
#define H 8
#define ROWS (BATCH * SQ)   // 16384
#define KSPLIT 8
#define KS_LEN (SK / KSPLIT)  // 256

// Scratch (allocation-free: __device__ globals)
__device__ float g_q[ROWS * H];
__device__ float g_k[ROWS * H];
__device__ float g_v[ROWS * H];
__device__ float g_pn[KSPLIT * ROWS * H];  // partial numerators
__device__ float g_pd[KSPLIT * ROWS];      // partial denominators

typedef unsigned long long ull;

__device__ __forceinline__ ull ffma2(ull a, ull b, ull c) {
    ull d;
    asm("fma.rn.f32x2 %0, %1, %2, %3;" : "=l"(d) : "l"(a), "l"(b), "l"(c));
    return d;
}
__device__ __forceinline__ ull fmul2(ull a, ull b) {
    ull d;
    asm("mul.rn.f32x2 %0, %1, %2;" : "=l"(d) : "l"(a), "l"(b));
    return d;
}
__device__ __forceinline__ float f2_lo(ull a) { return __uint_as_float((unsigned)(a & 0xffffffffull)); }
__device__ __forceinline__ float f2_hi(ull a) { return __uint_as_float((unsigned)(a >> 32)); }
__device__ __forceinline__ ull f2_pack(float lo, float hi) {
    ull p;
    asm("mov.b64 %0, {%1, %2};" : "=l"(p) : "r"(__float_as_uint(lo)), "r"(__float_as_uint(hi)));
    return p;
}

// ---------------------------------------------------------------------------
// Kernel 1: fused q/k/v projection. grid = 3 * 256 blocks x 256 threads.
//   path = blockIdx.x >> 8 selects (X, W, bias, Y). 64 rows/block,
//   8 rows/warp as four batches of two. Per batch the d-loop is split into
//   TWO halves of 512: per half only 8 LDG.128 are front-batched (32 regs),
//   keeping total thread state ~90 regs -> NO spills (R6's silent-spill bug)
//   while preserving MLP=8 for DRAM latency hiding.
//   W transposed in smem (+8 pad), staged with float4 loads.
// ---------------------------------------------------------------------------
#define PROJ_WPITCH 1032   // 1024 + 8 pad floats
__global__ void __launch_bounds__(256, 2) proj_fused_kernel(
    const float* __restrict__ x, const float* __restrict__ ctx,
    const float* __restrict__ Wq, const float* __restrict__ bq,
    const float* __restrict__ Wk, const float* __restrict__ bk,
    const float* __restrict__ Wv, const float* __restrict__ bv,
    float* __restrict__ q, float* __restrict__ k, float* __restrict__ v)
{
    __shared__ float sw[H * PROJ_WPITCH];   // 33 KB

    const int tid = threadIdx.x;
    const int warp = tid >> 5;
    const int lane = tid & 31;

    const int path = blockIdx.x >> 8;       // 0 = q, 1 = k, 2 = v
    const int blk  = blockIdx.x & 255;

    const float* X    = (path == 0) ? x  : ctx;
    const float* W    = (path == 0) ? Wq : (path == 1) ? Wk : Wv;
    const float* bias = (path == 0) ? bq : (path == 1) ? bk : bv;
    float*       Y    = (path == 0) ? q  : (path == 1) ? k  : v;

    // Stage W transposed via float4 global loads:
    //   i in [0, 2048): d = i>>1, hg = (i&1)*4 -> W[d*8 + hg .. +4]
    for (int i = tid; i < DIM * 2; i += 256) {
        int d = i >> 1, hg = (i & 1) * 4;
        float4 w4 = *reinterpret_cast<const float4*>(W + d * H + hg);
        sw[(hg + 0) * PROJ_WPITCH + d] = w4.x;
        sw[(hg + 1) * PROJ_WPITCH + d] = w4.y;
        sw[(hg + 2) * PROJ_WPITCH + d] = w4.z;
        sw[(hg + 3) * PROJ_WPITCH + d] = w4.w;
    }
    float bias_lane = (lane < H) ? bias[lane] : 0.0f;
    __syncthreads();

    const int block_row0 = blk * 64;

#pragma unroll 1
    for (int b2 = 0; b2 < 4; ++b2) {
        const int row0 = block_row0 + warp * 8 + b2 * 2;
        const float* xr0 = X + (size_t)row0 * DIM + lane * 4;

        ull acc0[H], acc1[H];
#pragma unroll
        for (int h = 0; h < H; ++h) { acc0[h] = 0ull; acc1[h] = 0ull; }

        // Two d-halves of 512; per half: 8 front-batched LDG.128 (32 regs)
#pragma unroll 1
        for (int half = 0; half < 2; ++half) {
            const int dbase = half * 512;
            ulonglong2 xv0[4], xv1[4];
#pragma unroll
            for (int u = 0; u < 4; ++u)
                xv0[u] = *reinterpret_cast<const ulonglong2*>(xr0 + dbase + u * 128);
#pragma unroll
            for (int u = 0; u < 4; ++u)
                xv1[u] = *reinterpret_cast<const ulonglong2*>(xr0 + DIM + dbase + u * 128);

#pragma unroll
            for (int u = 0; u < 4; ++u) {
                const int d = lane * 4 + dbase + u * 128;
#pragma unroll
                for (int h = 0; h < H; ++h) {
                    ulonglong2 wv = *reinterpret_cast<const ulonglong2*>(&sw[h * PROJ_WPITCH + d]);
                    acc0[h] = ffma2(xv0[u].x, wv.x, acc0[h]);
                    acc0[h] = ffma2(xv0[u].y, wv.y, acc0[h]);
                    acc1[h] = ffma2(xv1[u].x, wv.x, acc1[h]);
                    acc1[h] = ffma2(xv1[u].y, wv.y, acc1[h]);
                }
            }
        }

        // Reduce across lanes; lane h keeps head h's sum
#pragma unroll
        for (int r = 0; r < 2; ++r) {
            float keep = 0.0f;
#pragma unroll
            for (int h = 0; h < H; ++h) {
                ull a = r ? acc1[h] : acc0[h];
                float s = f2_lo(a) + f2_hi(a);
                s += __shfl_xor_sync(0xffffffffu, s, 16);
                s += __shfl_xor_sync(0xffffffffu, s, 8);
                s += __shfl_xor_sync(0xffffffffu, s, 4);
                s += __shfl_xor_sync(0xffffffffu, s, 2);
                s += __shfl_xor_sync(0xffffffffu, s, 1);
                if (lane == h) keep = s;
            }
            if (lane < H) Y[(size_t)(row0 + r) * H + lane] = keep + bias_lane;
        }
    }
}

// ---------------------------------------------------------------------------
// Kernel 2: attention partials with key-split.
//   grid = 8 batches x 16 qchunks x 8 ksplits = 1024 blocks x 128 threads.
//   One thread per query; each block covers 256 keys (tile in smem, 16 KB).
//   Softmax without max-subtraction -> split partials add exactly.
// ---------------------------------------------------------------------------
__global__ void __launch_bounds__(128) attn_part_kernel(
    const float* __restrict__ q, const float* __restrict__ k,
    const float* __restrict__ v, float* __restrict__ pn,
    float* __restrict__ pd)
{
    __shared__ float ks[KS_LEN * H];   // 8 KB
    __shared__ float vs[KS_LEN * H];   // 8 KB

    const int tid = threadIdx.x;
    const int bb = blockIdx.x >> 7;            // batch
    const int qc = (blockIdx.x >> 3) & 15;     // query chunk
    const int sp = blockIdx.x & 7;             // key split
    const int row = bb * SQ + qc * 128 + tid;
    const int kbase = bb * SK + sp * KS_LEN;

    // Cooperative tile load: 256 keys x 8 floats for k and v
    {
        const float4* kg = reinterpret_cast<const float4*>(k + (size_t)kbase * H);
        const float4* vg = reinterpret_cast<const float4*>(v + (size_t)kbase * H);
        float4* ks4 = reinterpret_cast<float4*>(ks);
        float4* vs4 = reinterpret_cast<float4*>(vs);
#pragma unroll
        for (int i = 0; i < (KS_LEN * H / 4) / 128; ++i) {
            ks4[tid + i * 128] = kg[tid + i * 128];
            vs4[tid + i * 128] = vg[tid + i * 128];
        }
    }

    // Query in registers as four f32x2 packs
    ulonglong2 qa = *reinterpret_cast<const ulonglong2*>(q + (size_t)row * H);
    ulonglong2 qb = *reinterpret_cast<const ulonglong2*>(q + (size_t)row * H + 4);
    const ull q01 = qa.x, q23 = qa.y, q45 = qb.x, q67 = qb.y;

    __syncthreads();

    ull acc0 = 0ull, acc1 = 0ull, acc2 = 0ull, acc3 = 0ull;
    float denom = 0.0f;

#pragma unroll 8
    for (int t = 0; t < KS_LEN; ++t) {
        ulonglong2 k0 = *reinterpret_cast<const ulonglong2*>(&ks[t * H]);
        ulonglong2 k1 = *reinterpret_cast<const ulonglong2*>(&ks[t * H + 4]);
        ull s2 = fmul2(q67, k1.y);
        s2 = ffma2(q45, k1.x, s2);
        s2 = ffma2(q23, k0.y, s2);
        s2 = ffma2(q01, k0.x, s2);
        float s = f2_lo(s2) + f2_hi(s2);
        float e = __expf(s);
        denom += e;
        ull e2 = f2_pack(e, e);
        ulonglong2 v0 = *reinterpret_cast<const ulonglong2*>(&vs[t * H]);
        ulonglong2 v1 = *reinterpret_cast<const ulonglong2*>(&vs[t * H + 4]);
        acc0 = ffma2(e2, v0.x, acc0);
        acc1 = ffma2(e2, v0.y, acc1);
        acc2 = ffma2(e2, v1.x, acc2);
        acc3 = ffma2(e2, v1.y, acc3);
    }

    float4 o0, o1;
    o0.x = f2_lo(acc0); o0.y = f2_hi(acc0);
    o0.z = f2_lo(acc1); o0.w = f2_hi(acc1);
    o1.x = f2_lo(acc2); o1.y = f2_hi(acc2);
    o1.z = f2_lo(acc3); o1.w = f2_hi(acc3);
    float* pnr = pn + ((size_t)sp * ROWS + row) * H;
    *reinterpret_cast<float4*>(pnr)     = o0;
    *reinterpret_cast<float4*>(pnr + 4) = o1;
    pd[(size_t)sp * ROWS + row] = denom;
}

// ---------------------------------------------------------------------------
// Kernel 3: combine split-K partials + output projection.
//   grid = 1024 blocks x 256 threads, 16 rows/block.
//   Fold parallelized: threads 0..127 each fetch one (row, split) partial
//   into smem; threads 0..15 then fold 8 splits from smem (LDS, not LDG).
//   All threads project with Wo slice in registers (8 x float4 per thread).
// ---------------------------------------------------------------------------
#define OUT_RPB 16
__global__ void __launch_bounds__(256) outproj_kernel(
    const float* __restrict__ pn, const float* __restrict__ pd,
    const float* __restrict__ Wo, const float* __restrict__ bo,
    float* __restrict__ out)
{
    __shared__ float ps[OUT_RPB][KSPLIT][12];  // 9 used, pad to 12
    __shared__ float a_sm[OUT_RPB][H];

    const int t = threadIdx.x;
    const int j = t * 4;
    const int row0 = blockIdx.x * OUT_RPB;

    if (t < OUT_RPB * KSPLIT) {
        const int r = t >> 3;
        const int s = t & 7;
        const int row = row0 + r;
        const float* p = pn + ((size_t)s * ROWS + row) * H;
        float4 a = *reinterpret_cast<const float4*>(p);
        float4 b = *reinterpret_cast<const float4*>(p + 4);
        ps[r][s][0] = a.x; ps[r][s][1] = a.y; ps[r][s][2] = a.z; ps[r][s][3] = a.w;
        ps[r][s][4] = b.x; ps[r][s][5] = b.y; ps[r][s][6] = b.z; ps[r][s][7] = b.w;
        ps[r][s][8] = pd[(size_t)s * ROWS + row];
    }

    float4 w[H];
#pragma unroll
    for (int h = 0; h < H; ++h)
        w[h] = *reinterpret_cast<const float4*>(Wo + h * DIM + j);
    const float4 b4 = *reinterpret_cast<const float4*>(bo + j);

    __syncthreads();

    if (t < OUT_RPB) {
        float n[H] = {0.f, 0.f, 0.f, 0.f, 0.f, 0.f, 0.f, 0.f};
        float den = 0.0f;
#pragma unroll
        for (int s = 0; s < KSPLIT; ++s) {
#pragma unroll
            for (int h = 0; h < H; ++h) n[h] += ps[t][s][h];
            den += ps[t][s][8];
        }
        const float inv = 1.0f / den;
#pragma unroll
        for (int h = 0; h < H; ++h) a_sm[t][h] = n[h] * inv;
    }
    __syncthreads();

#pragma unroll
    for (int r = 0; r < OUT_RPB; ++r) {
        const int row = row0 + r;
        float4 o = b4;
#pragma unroll
        for (int h = 0; h < H; ++h) {
            float ah = a_sm[r][h];
            o.x = fmaf(ah, w[h].x, o.x);
            o.y = fmaf(ah, w[h].y, o.y);
            o.z = fmaf(ah, w[h].z, o.z);
            o.w = fmaf(ah, w[h].w, o.w);
        }
        *reinterpret_cast<float4*>(out + (size_t)row * DIM + j) = o;
    }
}

// ---------------------------------------------------------------------------
extern "C" void kernel_launch(void* const* d_in, const int* in_sizes, int n_in,
                              void* d_out, int out_size)
{
    const float* x       = (const float*)d_in[0];
    const float* context = (const float*)d_in[1];
    const float* Wq      = (const float*)d_in[2];
    const float* bq      = (const float*)d_in[3];
    const float* Wk      = (const float*)d_in[4];
    const float* bk      = (const float*)d_in[5];
    const float* Wv      = (const float*)d_in[6];
    const float* bv      = (const float*)d_in[7];
    const float* Wo      = (const float*)d_in[8];
    const float* bo      = (const float*)d_in[9];
    float* out = (float*)d_out;

    float* q_p;  cudaGetSymbolAddress((void**)&q_p,  g_q);
    float* k_p;  cudaGetSymbolAddress((void**)&k_p,  g_k);
    float* v_p;  cudaGetSymbolAddress((void**)&v_p,  g_v);
    float* pn_p; cudaGetSymbolAddress((void**)&pn_p, g_pn);
    float* pd_p; cudaGetSymbolAddress((void**)&pd_p, g_pd);

    proj_fused_kernel<<<3 * 256, 256>>>(x, context, Wq, bq, Wk, bk, Wv, bv,
                                        q_p, k_p, v_p);
    attn_part_kernel<<<BATCH * 16 * KSPLIT, 128>>>(q_p, k_p, v_p, pn_p, pd_p);
    outproj_kernel<<<ROWS / OUT_RPB, 256>>>(pn_p, pd_p, Wo, bo, out);
}